// round 7
// baseline (speedup 1.0000x reference)
#include <cuda_runtime.h>
#include <cuda_bf16.h>
#include <stdint.h>
#include <math.h>

#define NBt 256
#define POS 676          // 26*26
#define LLt 624
#define DDc 128
#define CHc 256
#define HP  28           // padded grid 28x28
#define MT  64           // positions per CTA
#define NCONV 2704       // NBt*POS/MT (exact)

// ---- device-global scratch ----
__device__ float          g_Y  [(size_t)NBt*POS*DDc];      // residual stream, fp32
__device__ __nv_bfloat16  g_Ynp[(size_t)NBt*HP*HP*DDc];    // LN out, bf16, zero-padded
__device__ __nv_bfloat16  g_w3T[(size_t)4*9*CHc*DDc];      // [l][tap][co][ci]
__device__ __nv_bfloat16  g_w1T[(size_t)4*DDc*CHc];        // [l][d][co]
__device__ int            g_inv[POS];

// ---------------- PTX helpers (baseline PTX only) ----------------
__device__ __forceinline__ uint32_t s2u(const void* p){
  uint32_t a;
  asm("{ .reg .u64 t; cvta.to.shared.u64 t, %1; cvt.u32.u64 %0, t; }" : "=r"(a) : "l"(p));
  return a;
}
#define CP16(dst, src) asm volatile("cp.async.cg.shared.global [%0], [%1], 16;" :: "r"(dst), "l"(src) : "memory")
#define CP_COMMIT()    asm volatile("cp.async.commit_group;" ::: "memory")
#define CP_WAIT(n)     asm volatile("cp.async.wait_group %0;" :: "n"(n) : "memory")

__device__ __forceinline__ void ldsm4(uint32_t addr, uint32_t &r0, uint32_t &r1, uint32_t &r2, uint32_t &r3){
  asm volatile("ldmatrix.sync.aligned.m8n8.x4.shared.b16 {%0,%1,%2,%3}, [%4];"
    : "=r"(r0),"=r"(r1),"=r"(r2),"=r"(r3) : "r"(addr));
}
__device__ __forceinline__ void mma16816(float* c, uint32_t a0,uint32_t a1,uint32_t a2,uint32_t a3,
                                         uint32_t b0,uint32_t b1){
  asm volatile("mma.sync.aligned.m16n8k16.row.col.f32.bf16.bf16.f32 "
    "{%0,%1,%2,%3}, {%4,%5,%6,%7}, {%8,%9}, {%0,%1,%2,%3};"
    : "+f"(c[0]),"+f"(c[1]),"+f"(c[2]),"+f"(c[3])
    : "r"(a0),"r"(a1),"r"(a2),"r"(a3),"r"(b0),"r"(b1));
}

// ---------------- small kernels ----------------
__global__ void k_inv(const int* __restrict__ coords){
  int t = threadIdx.x;
  if (t < POS) g_inv[t] = -1;
  __syncthreads();
  if (t < LLt){
    int r = coords[2*t], c = coords[2*t+1];
    g_inv[r*26 + c] = t;
  }
}

// merged weight transpose+cast + g_Ynp border zeroing
__global__ void k_prep(const float* __restrict__ w3, const float* __restrict__ w1){
  int blk = blockIdx.x;
  if (blk < 4608){
    int idx = blk*256 + threadIdx.x;
    int ci = idx & 127;
    int co = (idx>>7) & 255;
    int lt = idx>>15;
    g_w3T[idx] = __float2bfloat16(w3[((size_t)lt*128 + ci)*256 + co]);
  } else if (blk < 5120){
    int idx = (blk-4608)*256 + threadIdx.x;
    int co = idx & 255;
    int d  = (idx>>8) & 127;
    int l  = idx>>15;
    g_w1T[idx] = __float2bfloat16(w1[((size_t)l*256 + co)*128 + d]);
  } else {
    int idx = (blk-5120)*256 + threadIdx.x;
    int c2 = idx & 63;
    int j  = (idx >> 6) % 108;
    int b  = (idx >> 6) / 108;
    int r, c;
    if      (j < 28){ r = 0;       c = j; }
    else if (j < 56){ r = 27;      c = j-28; }
    else if (j < 82){ r = j-56+1;  c = 0; }
    else            { r = j-82+1;  c = 27; }
    *(__nv_bfloat162*)(g_Ynp + (((size_t)b*HP + r)*HP + c)*DDc + c2*2) =
        __floats2bfloat162_rn(0.f, 0.f);
  }
}

// fused scatter + layer-0 LN
__global__ void k_fill_ln(const float* __restrict__ X, const float* __restrict__ P,
                          const float* __restrict__ scale, const float* __restrict__ bias){
  int cell = blockIdx.x*8 + (threadIdx.x>>5);
  int lane = threadIdx.x & 31;
  int b = cell/POS, sp = cell - b*POS;
  int li = g_inv[sp];
  const float* src = (li >= 0) ? (X + ((size_t)b*LLt + li)*DDc) : P;
  float v0=src[lane], v1=src[lane+32], v2=src[lane+64], v3=src[lane+96];
  float* y = g_Y + (size_t)cell*DDc;
  y[lane]=v0; y[lane+32]=v1; y[lane+64]=v2; y[lane+96]=v3;
  float s  = v0+v1+v2+v3;
  float s2 = v0*v0+v1*v1+v2*v2+v3*v3;
  #pragma unroll
  for (int o=16;o;o>>=1){ s += __shfl_xor_sync(~0u,s,o); s2 += __shfl_xor_sync(~0u,s2,o); }
  float mn = s*(1.f/128.f);
  float var = s2*(1.f/128.f) - mn*mn;
  float rs = rsqrtf(var + 1e-5f);
  int h = sp/26, w = sp - h*26;
  __nv_bfloat16* o = g_Ynp + (((size_t)b*HP + h+1)*HP + (w+1))*DDc;
  o[lane]    = __float2bfloat16((v0-mn)*rs*scale[lane]    + bias[lane]);
  o[lane+32] = __float2bfloat16((v1-mn)*rs*scale[lane+32] + bias[lane+32]);
  o[lane+64] = __float2bfloat16((v2-mn)*rs*scale[lane+64] + bias[lane+64]);
  o[lane+96] = __float2bfloat16((v3-mn)*rs*scale[lane+96] + bias[lane+96]);
}

// warp-per-cell LayerNorm (layers 1..3)
__global__ void k_ln(const float* __restrict__ scale, const float* __restrict__ bias){
  int cell = blockIdx.x*8 + (threadIdx.x>>5);
  int lane = threadIdx.x & 31;
  const float* x = g_Y + (size_t)cell*DDc;
  float v0=x[lane], v1=x[lane+32], v2=x[lane+64], v3=x[lane+96];
  float s  = v0+v1+v2+v3;
  float s2 = v0*v0+v1*v1+v2*v2+v3*v3;
  #pragma unroll
  for (int o=16;o;o>>=1){ s += __shfl_xor_sync(~0u,s,o); s2 += __shfl_xor_sync(~0u,s2,o); }
  float mn = s*(1.f/128.f);
  float var = s2*(1.f/128.f) - mn*mn;
  float rs = rsqrtf(var + 1e-5f);
  int b = cell/POS, sp = cell - b*POS;
  int h = sp/26, w = sp - h*26;
  __nv_bfloat16* o = g_Ynp + (((size_t)b*HP + h+1)*HP + (w+1))*DDc;
  o[lane]    = __float2bfloat16((v0-mn)*rs*scale[lane]    + bias[lane]);
  o[lane+32] = __float2bfloat16((v1-mn)*rs*scale[lane+32] + bias[lane+32]);
  o[lane+64] = __float2bfloat16((v2-mn)*rs*scale[lane+64] + bias[lane+64]);
  o[lane+96] = __float2bfloat16((v3-mn)*rs*scale[lane+96] + bias[lane+96]);
}

__global__ void k_gather(const int* __restrict__ coords, float* __restrict__ out){
  unsigned idx = blockIdx.x*256u + threadIdx.x;
  int c = idx & (DDc-1);
  int l = (idx >> 7) % LLt;
  int b = (idx >> 7) / LLt;
  int r = coords[2*l], cc = coords[2*l+1];
  out[idx] = g_Y[((size_t)b*POS + r*26 + cc)*DDc + c];
}

// ---------------- fused conv block: M=64 CTAs, 2 CTAs/SM for overlap ----------------
// 8 warps, warp tile 32x64. Single A (16KB) + single B (64KB) buffers; per-tap
// load exposure is hidden by the co-resident CTA. G (32KB) reuses A region;
// w1 tile reuses B region.
__global__ void __launch_bounds__(256,2) k_conv(
    int layer, const float* __restrict__ b3, const float* __restrict__ b1)
{
  extern __shared__ unsigned char smraw[];
  uint32_t sb0 = s2u(smraw);
  uint32_t pad = (0u - sb0) & 1023u;
  unsigned char* smem = smraw + pad;
  const uint32_t sbase = sb0 + pad;

  const int tid = threadIdx.x, lane = tid&31, wid = tid>>5;
  const int wm = wid & 1;          // 2-way M split (32 rows)
  const int wn = wid >> 1;         // 4-way N split (64 cols)
  const int lr = lane & 15;
  const int hi = lane >> 4;
  const int sw = lane & 7;

  enum { OFF_TAB=0, OFF_A=1024, OFF_G=1024, OFF_B=1024+32768 };  // end = 99328

  int* baseT = (int*)(smem + OFF_TAB);
  if (tid < MT){
    int p = blockIdx.x*MT + tid;
    int b = p/POS, sp = p - b*POS;
    int r = sp/26, c = sp - r*26;
    baseT[tid] = ((b*HP + r)*HP + c)*DDc;     // 3x3 window top-left elem offset
  }
  __syncthreads();

  const __nv_bfloat16* w3T = g_w3T + (size_t)layer*9*CHc*DDc;
  const __nv_bfloat16* w1T = g_w1T + (size_t)layer*DDc*CHc;

  float acc[2][8][4];
  #pragma unroll
  for (int a=0;a<2;a++)
    #pragma unroll
    for (int b=0;b<8;b++)
      #pragma unroll
      for (int q=0;q<4;q++) acc[a][b][q]=0.f;

  for (int t=0; t<9; t++){
    if (t>0) __syncthreads();            // buffers free (all warps done MMA t-1)
    // A tile [64 pos][128 ci] = 1024 16B chunks
    const int tapoff = ((t/3)*HP + (t%3))*DDc;
    #pragma unroll
    for (int it=0; it<4; it++){
      int seg = tid + it*256; int m = seg>>4, c = seg&15;
      uint32_t dst = sbase + OFF_A + m*256 + ((c ^ (m&7))<<4);
      CP16(dst, g_Ynp + (size_t)(baseT[m] + tapoff) + c*8);
    }
    // B tile [256 co][128 ci] = 4096 chunks
    const __nv_bfloat16* wsrc = w3T + (size_t)t*CHc*DDc;
    #pragma unroll
    for (int it=0; it<16; it++){
      int seg = tid + it*256; int row = seg>>4, c = seg&15;
      uint32_t dst = sbase + OFF_B + row*256 + ((c ^ (row&7))<<4);
      CP16(dst, wsrc + (size_t)row*DDc + c*8);
    }
    CP_COMMIT();
    CP_WAIT(0);
    __syncthreads();

    uint32_t Abase[2], Bbase[4];
    #pragma unroll
    for (int mb=0;mb<2;mb++) Abase[mb] = sbase + OFF_A + (wm*32 + mb*16 + lr)*256;
    #pragma unroll
    for (int nb2=0;nb2<4;nb2++) Bbase[nb2] = sbase + OFF_B + (wn*64 + nb2*16 + lr)*256;

    #pragma unroll
    for (int kb=0; kb<8; kb++){
      const uint32_t off = (uint32_t)(((2*kb + hi) ^ sw) << 4);
      uint32_t a[2][4], bf[4][4];
      #pragma unroll
      for (int mb=0;mb<2;mb++) ldsm4(Abase[mb]+off, a[mb][0],a[mb][1],a[mb][2],a[mb][3]);
      #pragma unroll
      for (int nb2=0;nb2<4;nb2++) ldsm4(Bbase[nb2]+off, bf[nb2][0],bf[nb2][1],bf[nb2][2],bf[nb2][3]);
      #pragma unroll
      for (int mb=0;mb<2;mb++){
        #pragma unroll
        for (int nb2=0;nb2<4;nb2++){
          mma16816(acc[mb][2*nb2  ], a[mb][0],a[mb][1],a[mb][2],a[mb][3], bf[nb2][0], bf[nb2][2]);
          mma16816(acc[mb][2*nb2+1], a[mb][0],a[mb][1],a[mb][2],a[mb][3], bf[nb2][1], bf[nb2][3]);
        }
      }
    }
  }
  __syncthreads();            // conv done; A and B regions now reusable

  // prefetch w1 tile [128 d][256 co] into OFF_B (overlaps with gelu below)
  #pragma unroll
  for (int it=0; it<16; it++){
    int seg = tid + it*256; int row = seg>>5, c = seg&31;
    uint32_t dst = sbase + OFF_B + row*512 + ((c ^ (row&7))<<4);
    CP16(dst, w1T + (size_t)row*CHc + c*8);
  }
  CP_COMMIT();

  // ---- epilogue 1: bias + exact gelu -> bf16 G [64 m][256 k] at OFF_G (32KB) ----
  {
    const int rq = lane>>2;
    #pragma unroll
    for (int mb=0;mb<2;mb++){
      const int r0 = wm*32 + mb*16 + rq;
      const int r1 = r0 + 8;
      #pragma unroll
      for (int nb=0;nb<8;nb++){
        const int col = wn*64 + nb*8 + 2*(lane&3);
        float2 bv = *(const float2*)(b3 + col);
        float v0 = acc[mb][nb][0] + bv.x;
        float v1 = acc[mb][nb][1] + bv.y;
        float v2 = acc[mb][nb][2] + bv.x;
        float v3 = acc[mb][nb][3] + bv.y;
        v0 = 0.5f*v0*(1.0f+erff(v0*0.7071067811865476f));
        v1 = 0.5f*v1*(1.0f+erff(v1*0.7071067811865476f));
        v2 = 0.5f*v2*(1.0f+erff(v2*0.7071067811865476f));
        v3 = 0.5f*v3*(1.0f+erff(v3*0.7071067811865476f));
        const int chunk = col>>3, wb = (col&7)*2;
        uint32_t o0 = (uint32_t)(r0*512 + ((chunk ^ (r0&7))<<4) + wb);
        uint32_t o1 = (uint32_t)(r1*512 + ((chunk ^ (r1&7))<<4) + wb);
        __nv_bfloat162 h0 = __floats2bfloat162_rn(v0, v1);
        __nv_bfloat162 h1 = __floats2bfloat162_rn(v2, v3);
        *(uint32_t*)(smem + OFF_G + o0) = *(uint32_t*)&h0;
        *(uint32_t*)(smem + OFF_G + o1) = *(uint32_t*)&h1;
      }
    }
  }
  CP_WAIT(0);                            // w1 tile resident
  __syncthreads();                       // G visible to all warps

  // ---- 1x1 GEMM: D2[64,128] = G[64,256] @ w1T^T (warp tile 32x32) ----
  float a2[2][4][4];
  #pragma unroll
  for (int a=0;a<2;a++)
    #pragma unroll
    for (int b=0;b<4;b++)
      #pragma unroll
      for (int q=0;q<4;q++) a2[a][b][q]=0.f;
  {
    uint32_t Gbase[2], Wbase[2];
    #pragma unroll
    for (int mb=0;mb<2;mb++) Gbase[mb] = sbase + OFF_G + (wm*32 + mb*16 + lr)*512;
    #pragma unroll
    for (int nb2=0;nb2<2;nb2++) Wbase[nb2] = sbase + OFF_B + (wn*32 + nb2*16 + lr)*512;

    #pragma unroll
    for (int kb=0; kb<16; kb++){
      const uint32_t off = (uint32_t)(((2*kb + hi) ^ sw) << 4);
      uint32_t a[2][4], bf[2][4];
      #pragma unroll
      for (int mb=0;mb<2;mb++) ldsm4(Gbase[mb]+off, a[mb][0],a[mb][1],a[mb][2],a[mb][3]);
      #pragma unroll
      for (int nb2=0;nb2<2;nb2++) ldsm4(Wbase[nb2]+off, bf[nb2][0],bf[nb2][1],bf[nb2][2],bf[nb2][3]);
      #pragma unroll
      for (int mb=0;mb<2;mb++){
        #pragma unroll
        for (int nb2=0;nb2<2;nb2++){
          mma16816(a2[mb][2*nb2  ], a[mb][0],a[mb][1],a[mb][2],a[mb][3], bf[nb2][0], bf[nb2][2]);
          mma16816(a2[mb][2*nb2+1], a[mb][0],a[mb][1],a[mb][2],a[mb][3], bf[nb2][1], bf[nb2][3]);
        }
      }
    }
  }

  // ---- epilogue 2: bias + residual RMW into g_Y ----
  {
    const int rq = lane>>2;
    #pragma unroll
    for (int mb=0;mb<2;mb++){
      const int r0 = wm*32 + mb*16 + rq;
      float* y0 = g_Y + ((size_t)blockIdx.x*MT + r0)*DDc;
      #pragma unroll
      for (int nb=0;nb<4;nb++){
        const int d = wn*32 + nb*8 + 2*(lane&3);
        float2 bv = *(const float2*)(b1 + d);
        float2 ya = *(float2*)(y0 + d);
        ya.x += a2[mb][nb][0] + bv.x;
        ya.y += a2[mb][nb][1] + bv.y;
        *(float2*)(y0 + d) = ya;
        float2 yb = *(float2*)(y0 + 8*DDc + d);
        yb.x += a2[mb][nb][2] + bv.x;
        yb.y += a2[mb][nb][3] + bv.y;
        *(float2*)(y0 + 8*DDc + d) = yb;
      }
    }
  }
}

// ---------------- launch ----------------
extern "C" void kernel_launch(void* const* d_in, const int* in_sizes, int n_in,
                              void* d_out, int out_size){
  const float* X        = (const float*)d_in[0];
  const int*   coords   = (const int*)  d_in[1];
  const float* P        = (const float*)d_in[2];
  const float* ln_scale = (const float*)d_in[3];
  const float* ln_bias  = (const float*)d_in[4];
  const float* w3       = (const float*)d_in[5];
  const float* b3       = (const float*)d_in[6];
  const float* w1       = (const float*)d_in[7];
  const float* b1       = (const float*)d_in[8];
  float* out = (float*)d_out;

  const int SMEM_SZ = 99328 + 1024;      // 98KB tiles + align slack
  cudaFuncSetAttribute(k_conv, cudaFuncAttributeMaxDynamicSharedMemorySize, SMEM_SZ);

  // launch order keeps index 3 (ncu's sample slot) = k_conv layer 0
  k_inv    <<<1, 1024>>>(coords);                                   // 0
  k_prep   <<<12032, 256>>>(w3, w1);                                // 1
  k_fill_ln<<<21632, 256>>>(X, P, ln_scale, ln_bias);               // 2
  k_conv   <<<NCONV, 256, SMEM_SZ>>>(0, b3, b1);                    // 3  <- profiled
  for (int l=1; l<4; l++){
    k_ln  <<<21632, 256>>>(ln_scale + l*DDc, ln_bias + l*DDc);
    k_conv<<<NCONV, 256, SMEM_SZ>>>(l, b3 + l*CHc, b1 + l*DDc);
  }
  k_gather<<<79872, 256>>>(coords, out);
}

// round 8
// speedup vs baseline: 1.0552x; 1.0552x over previous
#include <cuda_runtime.h>
#include <cuda_bf16.h>
#include <stdint.h>
#include <math.h>

#define NBt 256
#define POS 676          // 26*26
#define LLt 624
#define DDc 128
#define CHc 256
#define HP  28           // padded grid 28x28
#define NTILE 1352       // NBt*POS/128 (exact)

// ---- device-global scratch ----
__device__ float          g_Y  [(size_t)NBt*POS*DDc];      // residual stream, fp32
__device__ __nv_bfloat16  g_Ynp[(size_t)NBt*HP*HP*DDc];    // LN out, bf16, zero-padded
__device__ __nv_bfloat16  g_w3T[(size_t)4*9*CHc*DDc];      // [l][tap][co][ci]
__device__ __nv_bfloat16  g_w1T[(size_t)4*DDc*CHc];        // [l][d][co]
__device__ int            g_inv[POS];

// ---------------- PTX helpers (baseline PTX only) ----------------
__device__ __forceinline__ uint32_t s2u(const void* p){
  uint32_t a;
  asm("{ .reg .u64 t; cvta.to.shared.u64 t, %1; cvt.u32.u64 %0, t; }" : "=r"(a) : "l"(p));
  return a;
}
#define CP16(dst, src) asm volatile("cp.async.cg.shared.global [%0], [%1], 16;" :: "r"(dst), "l"(src) : "memory")
#define CP_COMMIT()    asm volatile("cp.async.commit_group;" ::: "memory")
#define CP_WAIT(n)     asm volatile("cp.async.wait_group %0;" :: "n"(n) : "memory")

__device__ __forceinline__ void ldsm4(uint32_t addr, uint32_t &r0, uint32_t &r1, uint32_t &r2, uint32_t &r3){
  asm volatile("ldmatrix.sync.aligned.m8n8.x4.shared.b16 {%0,%1,%2,%3}, [%4];"
    : "=r"(r0),"=r"(r1),"=r"(r2),"=r"(r3) : "r"(addr));
}
__device__ __forceinline__ void mma16816(float* c, uint32_t a0,uint32_t a1,uint32_t a2,uint32_t a3,
                                         uint32_t b0,uint32_t b1){
  asm volatile("mma.sync.aligned.m16n8k16.row.col.f32.bf16.bf16.f32 "
    "{%0,%1,%2,%3}, {%4,%5,%6,%7}, {%8,%9}, {%0,%1,%2,%3};"
    : "+f"(c[0]),"+f"(c[1]),"+f"(c[2]),"+f"(c[3])
    : "r"(a0),"r"(a1),"r"(a2),"r"(a3),"r"(b0),"r"(b1));
}

// ---- packed f32x2 ops ----
typedef unsigned long long u64;
__device__ __forceinline__ u64 pk2(float lo, float hi){
  u64 r; asm("mov.b64 %0, {%1, %2};" : "=l"(r) : "f"(lo), "f"(hi)); return r;
}
__device__ __forceinline__ void upk2(u64 v, float &lo, float &hi){
  asm("mov.b64 {%0, %1}, %2;" : "=f"(lo), "=f"(hi) : "l"(v));
}
__device__ __forceinline__ u64 mul2(u64 a, u64 b){
  u64 r; asm("mul.rn.f32x2 %0, %1, %2;" : "=l"(r) : "l"(a), "l"(b)); return r;
}
__device__ __forceinline__ u64 add2(u64 a, u64 b){
  u64 r; asm("add.rn.f32x2 %0, %1, %2;" : "=l"(r) : "l"(a), "l"(b)); return r;
}
__device__ __forceinline__ u64 fma2(u64 a, u64 b, u64 c){
  u64 r; asm("fma.rn.f32x2 %0, %1, %2, %3;" : "=l"(r) : "l"(a), "l"(b), "l"(c)); return r;
}

// branchless MUFU-free packed gelu: 0.5x(1+tanh(x(c0+c1 x^2))), tanh = Pade 7/6
__device__ __forceinline__ u64 gelu2(float v0, float v1){
  const u64 C0  = pk2(0.79788456f, 0.79788456f);
  const u64 C1  = pk2(0.035677408f, 0.035677408f);
  const u64 K378  = pk2(378.f, 378.f);
  const u64 K17325= pk2(17325.f, 17325.f);
  const u64 K135  = pk2(135135.f, 135135.f);
  const u64 K28   = pk2(28.f, 28.f);
  const u64 K3150 = pk2(3150.f, 3150.f);
  const u64 K62370= pk2(62370.f, 62370.f);
  const u64 NTWO  = pk2(-2.f, -2.f);
  const u64 NONE  = pk2(-1.f, -1.f);
  const u64 HALF  = pk2(0.5f, 0.5f);

  u64 x  = pk2(v0, v1);
  u64 s  = mul2(x, x);
  u64 z  = mul2(x, fma2(C1, s, C0));
  u64 w  = mul2(z, z);
  u64 num = mul2(z, fma2(w, fma2(w, add2(w, K378), K17325), K135));
  u64 den = fma2(w, fma2(w, fma2(w, K28, K3150), K62370), K135);
  // rcp(den): magic + 2 Newton
  float dl, dh; upk2(den, dl, dh);
  float yl = __int_as_float(0x7EF311C3 - __float_as_int(dl));
  float yh = __int_as_float(0x7EF311C3 - __float_as_int(dh));
  u64 y  = pk2(yl, yh);
  u64 nd = mul2(den, NONE);
  y = mul2(y, fma2(nd, y, pk2(2.f,2.f)));
  y = mul2(y, fma2(nd, y, pk2(2.f,2.f)));
  (void)NTWO;
  u64 th = mul2(num, y);
  u64 hx = mul2(x, HALF);
  return fma2(th, hx, hx);       // 0.5x + 0.5x*tanh
}

// ---------------- small kernels ----------------
__global__ void k_inv(const int* __restrict__ coords){
  int t = threadIdx.x;
  if (t < POS) g_inv[t] = -1;
  __syncthreads();
  if (t < LLt){
    int r = coords[2*t], c = coords[2*t+1];
    g_inv[r*26 + c] = t;
  }
}

// merged weight transpose+cast + g_Ynp border zeroing
__global__ void k_prep(const float* __restrict__ w3, const float* __restrict__ w1){
  int blk = blockIdx.x;
  if (blk < 4608){
    int idx = blk*256 + threadIdx.x;
    int ci = idx & 127;
    int co = (idx>>7) & 255;
    int lt = idx>>15;
    g_w3T[idx] = __float2bfloat16(w3[((size_t)lt*128 + ci)*256 + co]);
  } else if (blk < 5120){
    int idx = (blk-4608)*256 + threadIdx.x;
    int co = idx & 255;
    int d  = (idx>>8) & 127;
    int l  = idx>>15;
    g_w1T[idx] = __float2bfloat16(w1[((size_t)l*256 + co)*128 + d]);
  } else {
    int idx = (blk-5120)*256 + threadIdx.x;
    int c2 = idx & 63;
    int j  = (idx >> 6) % 108;
    int b  = (idx >> 6) / 108;
    int r, c;
    if      (j < 28){ r = 0;       c = j; }
    else if (j < 56){ r = 27;      c = j-28; }
    else if (j < 82){ r = j-56+1;  c = 0; }
    else            { r = j-82+1;  c = 27; }
    *(__nv_bfloat162*)(g_Ynp + (((size_t)b*HP + r)*HP + c)*DDc + c2*2) =
        __floats2bfloat162_rn(0.f, 0.f);
  }
}

// fused scatter + layer-0 LN
__global__ void k_fill_ln(const float* __restrict__ X, const float* __restrict__ P,
                          const float* __restrict__ scale, const float* __restrict__ bias){
  int cell = blockIdx.x*8 + (threadIdx.x>>5);
  int lane = threadIdx.x & 31;
  int b = cell/POS, sp = cell - b*POS;
  int li = g_inv[sp];
  const float* src = (li >= 0) ? (X + ((size_t)b*LLt + li)*DDc) : P;
  float v0=src[lane], v1=src[lane+32], v2=src[lane+64], v3=src[lane+96];
  float* y = g_Y + (size_t)cell*DDc;
  y[lane]=v0; y[lane+32]=v1; y[lane+64]=v2; y[lane+96]=v3;
  float s  = v0+v1+v2+v3;
  float s2 = v0*v0+v1*v1+v2*v2+v3*v3;
  #pragma unroll
  for (int o=16;o;o>>=1){ s += __shfl_xor_sync(~0u,s,o); s2 += __shfl_xor_sync(~0u,s2,o); }
  float mn = s*(1.f/128.f);
  float var = s2*(1.f/128.f) - mn*mn;
  float rs = rsqrtf(var + 1e-5f);
  int h = sp/26, w = sp - h*26;
  __nv_bfloat16* o = g_Ynp + (((size_t)b*HP + h+1)*HP + (w+1))*DDc;
  o[lane]    = __float2bfloat16((v0-mn)*rs*scale[lane]    + bias[lane]);
  o[lane+32] = __float2bfloat16((v1-mn)*rs*scale[lane+32] + bias[lane+32]);
  o[lane+64] = __float2bfloat16((v2-mn)*rs*scale[lane+64] + bias[lane+64]);
  o[lane+96] = __float2bfloat16((v3-mn)*rs*scale[lane+96] + bias[lane+96]);
}

// warp-per-cell LayerNorm (layers 1..3)
__global__ void k_ln(const float* __restrict__ scale, const float* __restrict__ bias){
  int cell = blockIdx.x*8 + (threadIdx.x>>5);
  int lane = threadIdx.x & 31;
  const float* x = g_Y + (size_t)cell*DDc;
  float v0=x[lane], v1=x[lane+32], v2=x[lane+64], v3=x[lane+96];
  float s  = v0+v1+v2+v3;
  float s2 = v0*v0+v1*v1+v2*v2+v3*v3;
  #pragma unroll
  for (int o=16;o;o>>=1){ s += __shfl_xor_sync(~0u,s,o); s2 += __shfl_xor_sync(~0u,s2,o); }
  float mn = s*(1.f/128.f);
  float var = s2*(1.f/128.f) - mn*mn;
  float rs = rsqrtf(var + 1e-5f);
  int b = cell/POS, sp = cell - b*POS;
  int h = sp/26, w = sp - h*26;
  __nv_bfloat16* o = g_Ynp + (((size_t)b*HP + h+1)*HP + (w+1))*DDc;
  o[lane]    = __float2bfloat16((v0-mn)*rs*scale[lane]    + bias[lane]);
  o[lane+32] = __float2bfloat16((v1-mn)*rs*scale[lane+32] + bias[lane+32]);
  o[lane+64] = __float2bfloat16((v2-mn)*rs*scale[lane+64] + bias[lane+64]);
  o[lane+96] = __float2bfloat16((v3-mn)*rs*scale[lane+96] + bias[lane+96]);
}

__global__ void k_gather(const int* __restrict__ coords, float* __restrict__ out){
  unsigned idx = blockIdx.x*256u + threadIdx.x;
  int c = idx & (DDc-1);
  int l = (idx >> 7) % LLt;
  int b = (idx >> 7) / LLt;
  int r = coords[2*l], cc = coords[2*l+1];
  out[idx] = g_Y[((size_t)b*POS + r*26 + cc)*DDc + c];
}

// ---------------- fused conv block via mma.sync, 16 warps (32x64 warp tiles) ----------------
__global__ void __launch_bounds__(512,1) k_conv(
    int layer, const float* __restrict__ b3, const float* __restrict__ b1)
{
  extern __shared__ unsigned char smraw[];
  uint32_t sb0 = s2u(smraw);
  uint32_t pad = (0u - sb0) & 1023u;
  unsigned char* smem = smraw + pad;
  const uint32_t sbase = sb0 + pad;

  const int tid = threadIdx.x, lane = tid&31, wid = tid>>5;
  const int wm = wid & 3;          // 4-way M split (32 rows each)
  const int wn = wid >> 2;         // 4-way N split (64 cols each)
  const int lr = lane & 15;
  const int hi = lane >> 4;
  const int sw = lane & 7;

  enum { OFF_TAB=0, OFF_A0=1024, OFF_A1=1024+32768,
         OFF_B0=1024+65536, OFF_B1=1024+65536+65536 };   // end = 197632

  int* baseT = (int*)(smem + OFF_TAB);
  if (tid < 128){
    int p = blockIdx.x*128 + tid;
    int b = p/POS, sp = p - b*POS;
    int r = sp/26, c = sp - r*26;
    baseT[tid] = ((b*HP + r)*HP + c)*DDc;     // 3x3 window top-left elem offset
  }
  __syncthreads();

  const __nv_bfloat16* w3T = g_w3T + (size_t)layer*9*CHc*DDc;
  const __nv_bfloat16* w1T = g_w1T + (size_t)layer*DDc*CHc;

  #define LOAD_TAP(T_, AOFF, BOFF) do{                                          \
    const int tapoff = (((T_)/3)*HP + ((T_)%3))*DDc;                             \
    _Pragma("unroll")                                                            \
    for (int it=0; it<4; it++){                                                  \
      int seg = tid + it*512; int m = seg>>4, c = seg&15;                        \
      const __nv_bfloat16* src = g_Ynp + (size_t)(baseT[m] + tapoff) + c*8;      \
      uint32_t dst = sbase + (AOFF) + m*256 + ((c ^ (m&7))<<4);                  \
      CP16(dst, src);                                                            \
    }                                                                            \
    const __nv_bfloat16* wsrc = w3T + (size_t)(T_)*CHc*DDc;                      \
    _Pragma("unroll")                                                            \
    for (int it=0; it<8; it++){                                                  \
      int seg = tid + it*512; int row = seg>>4, c = seg&15;                      \
      uint32_t dst = sbase + (BOFF) + row*256 + ((c ^ (row&7))<<4);              \
      CP16(dst, wsrc + (size_t)row*DDc + c*8);                                   \
    }                                                                            \
  }while(0)

  float acc[2][8][4];
  #pragma unroll
  for (int a=0;a<2;a++)
    #pragma unroll
    for (int b=0;b<8;b++)
      #pragma unroll
      for (int q=0;q<4;q++) acc[a][b][q]=0.f;

  LOAD_TAP(0, OFF_A0, OFF_B0); CP_COMMIT();

  for (int t=0; t<9; t++){
    if (t>0) __syncthreads();
    if (t<8){
      if ((t+1)&1) LOAD_TAP(t+1, OFF_A1, OFF_B1);
      else         LOAD_TAP(t+1, OFF_A0, OFF_B0);
      CP_COMMIT();
    } else {
      // prefetch w1 tile [128 d][256 co] into B1
      #pragma unroll
      for (int it=0; it<8; it++){
        int seg = tid + it*512; int row = seg>>5, c = seg&31;
        uint32_t dst = sbase + OFF_B1 + row*512 + ((c ^ (row&7))<<4);
        CP16(dst, w1T + (size_t)row*CHc + c*8);
      }
      CP_COMMIT();
    }
    CP_WAIT(1);
    __syncthreads();

    const uint32_t abuf = sbase + ((t&1)? OFF_A1 : OFF_A0);
    const uint32_t bbuf = sbase + ((t&1)? OFF_B1 : OFF_B0);
    uint32_t Abase[2], Bbase[4];
    #pragma unroll
    for (int mb=0;mb<2;mb++) Abase[mb] = abuf + (wm*32 + mb*16 + lr)*256;
    #pragma unroll
    for (int nb2=0;nb2<4;nb2++) Bbase[nb2] = bbuf + (wn*64 + nb2*16 + lr)*256;

    #pragma unroll
    for (int kb=0; kb<8; kb++){
      const uint32_t off = (uint32_t)(((2*kb + hi) ^ sw) << 4);
      uint32_t a[2][4], bf[4][4];
      #pragma unroll
      for (int mb=0;mb<2;mb++) ldsm4(Abase[mb]+off, a[mb][0],a[mb][1],a[mb][2],a[mb][3]);
      #pragma unroll
      for (int nb2=0;nb2<4;nb2++) ldsm4(Bbase[nb2]+off, bf[nb2][0],bf[nb2][1],bf[nb2][2],bf[nb2][3]);
      #pragma unroll
      for (int mb=0;mb<2;mb++){
        #pragma unroll
        for (int nb2=0;nb2<4;nb2++){
          mma16816(acc[mb][2*nb2  ], a[mb][0],a[mb][1],a[mb][2],a[mb][3], bf[nb2][0], bf[nb2][2]);
          mma16816(acc[mb][2*nb2+1], a[mb][0],a[mb][1],a[mb][2],a[mb][3], bf[nb2][1], bf[nb2][3]);
        }
      }
    }
  }
  __syncthreads();

  // ---- epilogue 1: bias + packed fast gelu -> bf16 G [128 m][256 k] at OFF_A0 ----
  {
    const int rq = lane>>2;
    #pragma unroll
    for (int mb=0;mb<2;mb++){
      const int r0 = wm*32 + mb*16 + rq;
      const int r1 = r0 + 8;
      #pragma unroll
      for (int nb=0;nb<8;nb++){
        const int col = wn*64 + nb*8 + 2*(lane&3);
        float2 bv = *(const float2*)(b3 + col);
        u64 g0 = gelu2(acc[mb][nb][0] + bv.x, acc[mb][nb][1] + bv.y);
        u64 g1 = gelu2(acc[mb][nb][2] + bv.x, acc[mb][nb][3] + bv.y);
        float v0, v1, v2, v3;
        upk2(g0, v0, v1);
        upk2(g1, v2, v3);
        const int chunk = col>>3, wb = (col&7)*2;
        uint32_t o0 = (uint32_t)(r0*512 + ((chunk ^ (r0&7))<<4) + wb);
        uint32_t o1 = (uint32_t)(r1*512 + ((chunk ^ (r1&7))<<4) + wb);
        __nv_bfloat162 h0 = __floats2bfloat162_rn(v0, v1);
        __nv_bfloat162 h1 = __floats2bfloat162_rn(v2, v3);
        *(uint32_t*)(smem + OFF_A0 + o0) = *(uint32_t*)&h0;
        *(uint32_t*)(smem + OFF_A0 + o1) = *(uint32_t*)&h1;
      }
    }
  }
  CP_WAIT(0);                            // w1 tile resident
  __syncthreads();                       // G visible to all warps

  // ---- 1x1 GEMM: D2[128,128] = G[128,256] @ w1T^T (warp tile 32x32) ----
  float a2[2][4][4];
  #pragma unroll
  for (int a=0;a<2;a++)
    #pragma unroll
    for (int b=0;b<4;b++)
      #pragma unroll
      for (int q=0;q<4;q++) a2[a][b][q]=0.f;
  {
    uint32_t Gbase[2], Wbase[2];
    #pragma unroll
    for (int mb=0;mb<2;mb++) Gbase[mb] = sbase + OFF_A0 + (wm*32 + mb*16 + lr)*512;
    #pragma unroll
    for (int nb2=0;nb2<2;nb2++) Wbase[nb2] = sbase + OFF_B1 + (wn*32 + nb2*16 + lr)*512;

    #pragma unroll
    for (int kb=0; kb<16; kb++){
      const uint32_t off = (uint32_t)(((2*kb + hi) ^ sw) << 4);
      uint32_t a[2][4], bf[2][4];
      #pragma unroll
      for (int mb=0;mb<2;mb++) ldsm4(Gbase[mb]+off, a[mb][0],a[mb][1],a[mb][2],a[mb][3]);
      #pragma unroll
      for (int nb2=0;nb2<2;nb2++) ldsm4(Wbase[nb2]+off, bf[nb2][0],bf[nb2][1],bf[nb2][2],bf[nb2][3]);
      #pragma unroll
      for (int mb=0;mb<2;mb++){
        #pragma unroll
        for (int nb2=0;nb2<2;nb2++){
          mma16816(a2[mb][2*nb2  ], a[mb][0],a[mb][1],a[mb][2],a[mb][3], bf[nb2][0], bf[nb2][2]);
          mma16816(a2[mb][2*nb2+1], a[mb][0],a[mb][1],a[mb][2],a[mb][3], bf[nb2][1], bf[nb2][3]);
        }
      }
    }
  }

  // ---- epilogue 2: bias + residual RMW into g_Y ----
  {
    const int rq = lane>>2;
    #pragma unroll
    for (int mb=0;mb<2;mb++){
      const int r0 = wm*32 + mb*16 + rq;
      float* y0 = g_Y + ((size_t)blockIdx.x*128 + r0)*DDc;
      #pragma unroll
      for (int nb=0;nb<4;nb++){
        const int d = wn*32 + nb*8 + 2*(lane&3);
        float2 bv = *(const float2*)(b1 + d);
        float2 ya = *(float2*)(y0 + d);
        ya.x += a2[mb][nb][0] + bv.x;
        ya.y += a2[mb][nb][1] + bv.y;
        *(float2*)(y0 + d) = ya;
        float2 yb = *(float2*)(y0 + 8*DDc + d);
        yb.x += a2[mb][nb][2] + bv.x;
        yb.y += a2[mb][nb][3] + bv.y;
        *(float2*)(y0 + 8*DDc + d) = yb;
      }
    }
  }
  #undef LOAD_TAP
}

// ---------------- launch ----------------
extern "C" void kernel_launch(void* const* d_in, const int* in_sizes, int n_in,
                              void* d_out, int out_size){
  const float* X        = (const float*)d_in[0];
  const int*   coords   = (const int*)  d_in[1];
  const float* P        = (const float*)d_in[2];
  const float* ln_scale = (const float*)d_in[3];
  const float* ln_bias  = (const float*)d_in[4];
  const float* w3       = (const float*)d_in[5];
  const float* b3       = (const float*)d_in[6];
  const float* w1       = (const float*)d_in[7];
  const float* b1       = (const float*)d_in[8];
  float* out = (float*)d_out;

  const int SMEM_SZ = 197632 + 1024;
  cudaFuncSetAttribute(k_conv, cudaFuncAttributeMaxDynamicSharedMemorySize, SMEM_SZ);

  // launch order keeps index 3 (ncu's sample slot) = k_conv layer 0
  k_inv    <<<1, 1024>>>(coords);                                   // 0
  k_prep   <<<12032, 256>>>(w3, w1);                                // 1
  k_fill_ln<<<21632, 256>>>(X, P, ln_scale, ln_bias);               // 2
  k_conv   <<<NTILE, 512, SMEM_SZ>>>(0, b3, b1);                    // 3  <- profiled
  for (int l=1; l<4; l++){
    k_ln  <<<21632, 256>>>(ln_scale + l*DDc, ln_bias + l*DDc);
    k_conv<<<NTILE, 512, SMEM_SZ>>>(l, b3 + l*CHc, b1 + l*DDc);
  }
  k_gather<<<79872, 256>>>(coords, out);
}